// round 7
// baseline (speedup 1.0000x reference)
#include <cuda_runtime.h>
#include <cstdint>

#define TT   512
#define BB   128
#define II   256
#define HH   512
#define HXX  768
#define NCTA 128     // one CTA per 4 H-columns
#define JPC  4       // H columns per CTA
#define GCN  16      // gate-columns per CTA (4 gates * JPC)
#define NTHR 256
#define KC   32      // k-chunk
#define WROW 772     // padded Ws row (HXX + 4)
#define VPAD 36      // padded Vs row
#define VS_ELEMS (BB * VPAD)            // 4608 floats per buffer
#define WS_ELEMS (GCN * WROW)           // 12352 floats
#define SMEM_FLOATS (WS_ELEMS + 2 * VS_ELEMS)
#define SMEM_BYTES  (SMEM_FLOATS * 4)   // 86272 bytes

// Scratch (no allocations allowed): cell state + transposed packed weights.
__device__ float g_C[BB * HH];
__device__ float g_Wpack[4 * HH * HXX];   // [g][j][k], k contiguous

// f32x2 packed FMA: 2 MACs/instr (FFMA2) — doubles fp32 throughput on sm_103a.
#define FMA2(acc, a, b) \
    asm("fma.rn.f32x2 %0, %1, %2, %0;" : "+l"(acc) : "l"(a), "l"(b))

// ---------------------------------------------------------------------------
// One-time (per launch) weight transpose: Wg[k*H + j] -> g_Wpack[(g*H+j)*HX + k]
// ---------------------------------------------------------------------------
__global__ void pack_weights(const float* __restrict__ Wf, const float* __restrict__ Wi,
                             const float* __restrict__ Wc, const float* __restrict__ Wo) {
    __shared__ float tile[32][33];
    const int g  = blockIdx.z;
    const float* W = (g == 0) ? Wf : (g == 1) ? Wi : (g == 2) ? Wc : Wo;
    const int j0 = blockIdx.x * 32;
    const int k0 = blockIdx.y * 32;
    const int tx = threadIdx.x, ty0 = threadIdx.y;
    #pragma unroll
    for (int ty = ty0; ty < 32; ty += 8)
        tile[ty][tx] = W[(size_t)(k0 + ty) * HH + (j0 + tx)];
    __syncthreads();
    #pragma unroll
    for (int ty = ty0; ty < 32; ty += 8)
        g_Wpack[(size_t)(g * HH + j0 + ty) * HXX + (k0 + tx)] = tile[tx][ty];
}

// ---------------------------------------------------------------------------
// Per-step kernel. Chunk c in [0,16): v = h_{t-1} (from out[t-1]);
// chunk c in [16,24): v = x[t]. Matches hx = concat([h, x]).
// ---------------------------------------------------------------------------
__device__ __forceinline__ void load_chunk(float4 pref[4], const float* __restrict__ x,
                                           const float* __restrict__ out,
                                           int t, int c, int tid) {
    if (c < 16) {
        const float* src = out + (size_t)(t - 1) * (BB * HH) + c * KC;
        #pragma unroll
        for (int n = 0; n < 4; n++) {
            const int idx = tid + n * NTHR, b = idx >> 3, q = idx & 7;
            pref[n] = *(const float4*)(src + (size_t)b * HH + q * 4);
        }
    } else {
        const float* src = x + (size_t)t * (BB * II) + (c - 16) * KC;
        #pragma unroll
        for (int n = 0; n < 4; n++) {
            const int idx = tid + n * NTHR, b = idx >> 3, q = idx & 7;
            pref[n] = *(const float4*)(src + (size_t)b * II + q * 4);
        }
    }
}

__device__ __forceinline__ void store_chunk(float* vs, int buf, const float4 pref[4], int tid) {
    #pragma unroll
    for (int n = 0; n < 4; n++) {
        const int idx = tid + n * NTHR, b = idx >> 3, q = idx & 7;
        *(float4*)(vs + buf * VS_ELEMS + b * VPAD + q * 4) = pref[n];
    }
}

__global__ void __launch_bounds__(NTHR, 1)
lstm_step(const float* __restrict__ x,
          const float* __restrict__ bf, const float* __restrict__ bi_,
          const float* __restrict__ bc, const float* __restrict__ bo,
          float* __restrict__ out, int t)
{
    extern __shared__ float sm[];
    float* Ws = sm;                 // [GCN][WROW]
    float* vs = sm + WS_ELEMS;      // 2 x [BB][VPAD]

    const int tid = threadIdx.x;
    const int cid = blockIdx.x;
    const int j0  = cid * JPC;
    const int tx  = tid & 7;        // 8 gc-groups, 2 gate-cols each
    const int ty  = tid >> 3;       // 32 b-groups; thread owns b = ty + 32*bi

    // Stage this CTA's 16 weight columns (49KB) from packed layout — coalesced.
    {
        const float4* wp = (const float4*)g_Wpack;
        #pragma unroll
        for (int it = 0; it < (GCN * (HXX / 4)) / NTHR; ++it) {   // 12 iters
            const int idx = tid + it * NTHR;
            const int gc  = idx / (HXX / 4);
            const int k4  = idx % (HXX / 4);
            const int g = gc >> 2, jj = gc & 3;
            *(float4*)(Ws + gc * WROW + k4 * 4) =
                wp[(size_t)(g * HH + j0 + jj) * (HXX / 4) + k4];
        }
    }

    // Dual-lane accumulators (even-k / odd-k partials); bias in low lane.
    unsigned long long acc[2][4];
    #pragma unroll
    for (int gci = 0; gci < 2; gci++) {
        const int gc = 2 * tx + gci;
        const int g = gc >> 2, jj = gc & 3;
        const float* bp = (g == 0) ? bf : (g == 1) ? bi_ : (g == 2) ? bc : bo;
        const unsigned long long u = (unsigned long long)__float_as_uint(bp[j0 + jj]);
        #pragma unroll
        for (int bi = 0; bi < 4; bi++) acc[gci][bi] = u;
    }

    const int c0 = (t == 0) ? 16 : 0;   // h_0 = 0 -> skip h chunks at t=0
    float4 pref[4];
    load_chunk(pref, x, out, t, c0, tid);
    store_chunk(vs, 0, pref, tid);
    __syncthreads();

    for (int c = c0; c < 24; ++c) {
        const int buf = (c - c0) & 1;
        if (c + 1 < 24) load_chunk(pref, x, out, t, c + 1, tid);

        const float* wr0 = Ws + (2 * tx) * WROW + c * KC;
        const float* wr1 = wr0 + WROW;
        const float* vb  = vs + buf * VS_ELEMS + ty * VPAD;

        #pragma unroll
        for (int kk = 0; kk < KC; kk += 4) {
            const ulonglong2 w0 = *(const ulonglong2*)(wr0 + kk);
            const ulonglong2 w1 = *(const ulonglong2*)(wr1 + kk);
            #pragma unroll
            for (int bi = 0; bi < 4; bi++) {
                const ulonglong2 v = *(const ulonglong2*)(vb + bi * (32 * VPAD) + kk);
                FMA2(acc[0][bi], w0.x, v.x);
                FMA2(acc[0][bi], w0.y, v.y);
                FMA2(acc[1][bi], w1.x, v.x);
                FMA2(acc[1][bi], w1.y, v.y);
            }
        }

        if (c + 1 < 24) {
            store_chunk(vs, buf ^ 1, pref, tid);
            __syncthreads();
        }
    }

    // Gate exchange via smem (reuse vs buffer 0 — last compute used buffer 1).
    float* gsm = vs;   // gsm[gc * BB + b]
    #pragma unroll
    for (int gci = 0; gci < 2; gci++) {
        #pragma unroll
        for (int bi = 0; bi < 4; bi++) {
            const unsigned long long a = acc[gci][bi];
            const float lo = __uint_as_float((unsigned)(a & 0xffffffffu));
            const float hi = __uint_as_float((unsigned)(a >> 32));
            gsm[(2 * tx + gci) * BB + (ty + 32 * bi)] = lo + hi;
        }
    }
    __syncthreads();

    // Elementwise LSTM update: f,i,c,o -> C, h. 512 cells / CTA, 2 per thread.
    const size_t outbase = (size_t)t * (BB * HH);
    #pragma unroll
    for (int cell = tid; cell < BB * JPC; cell += NTHR) {
        const int b = cell >> 2, jj = cell & 3;
        const float fg = gsm[(0 * 4 + jj) * BB + b];
        const float ig = gsm[(1 * 4 + jj) * BB + b];
        const float cg = gsm[(2 * 4 + jj) * BB + b];
        const float og = gsm[(3 * 4 + jj) * BB + b];
        const float fs = 1.0f / (1.0f + expf(-fg));
        const float is = 1.0f / (1.0f + expf(-ig));
        const float os = 1.0f / (1.0f + expf(-og));
        const float Cold = (t == 0) ? 0.0f : g_C[b * HH + j0 + jj];
        const float Cnew = fs * Cold + is * tanhf(cg);
        g_C[b * HH + j0 + jj] = Cnew;
        out[outbase + (size_t)b * HH + j0 + jj] = os * tanhf(Cnew);
    }
}

// ---------------------------------------------------------------------------
extern "C" void kernel_launch(void* const* d_in, const int* in_sizes, int n_in,
                              void* d_out, int out_size) {
    (void)in_sizes; (void)n_in; (void)out_size;
    const float* x  = (const float*)d_in[0];
    const float* Wf = (const float*)d_in[1];
    const float* bf = (const float*)d_in[2];
    const float* Wi = (const float*)d_in[3];
    const float* bi = (const float*)d_in[4];
    const float* Wc = (const float*)d_in[5];
    const float* bc = (const float*)d_in[6];
    const float* Wo = (const float*)d_in[7];
    const float* bo = (const float*)d_in[8];
    float* out = (float*)d_out;

    // Opt in to >48KB dynamic smem (idempotent; not a stream op — capture-safe).
    cudaFuncSetAttribute(lstm_step, cudaFuncAttributeMaxDynamicSharedMemorySize, SMEM_BYTES);

    pack_weights<<<dim3(HH / 32, HXX / 32, 4), dim3(32, 8)>>>(Wf, Wi, Wc, Wo);
    for (int t = 0; t < TT; ++t)
        lstm_step<<<NCTA, NTHR, SMEM_BYTES>>>(x, bf, bi, bc, bo, out, t);
}

// round 8
// speedup vs baseline: 1.3967x; 1.3967x over previous
#include <cuda_runtime.h>
#include <cstdint>

#define TT   512
#define BB   128
#define II   256
#define HH   512
#define HXX  768
#define NCTA 128      // one CTA per 4 H-columns; all co-resident (<=148 SMs)
#define JPC  4
#define GCN  16       // gate-cols per CTA (4 gates * 4 cols)
#define NTHR 512      // 16 warps: 2 k-halves x 256
#define KC   64       // k-chunk per half
#define WROW 772      // padded weight row (768+4)
#define VROW 68       // padded v row (64+4)
#define VS_HALF (BB * VROW)            // 8704 floats per (buf,kg) tile
#define WS_ELEMS (GCN * WROW)          // 12352 floats
#define SMEM_FLOATS (WS_ELEMS + 4 * VS_HALF)
#define SMEM_BYTES  (SMEM_FLOATS * 4)  // 188672 bytes (< 227KB cap)

// Device scratch (no allocations allowed anywhere).
__device__ float    g_C[BB * HH];
__device__ float    g_Wpack[4 * HH * HXX];   // [g][j][k], k contiguous
__device__ unsigned g_bar;

// f32x2 packed FMA (FFMA2): 2 MACs/instr.
#define FMA2(acc, a, b) \
    asm("fma.rn.f32x2 %0, %1, %2, %0;" : "+l"(acc) : "l"(a), "l"(b))

__global__ void reset_bar() { g_bar = 0u; }

// ---------------------------------------------------------------------------
// One-time weight transpose: Wg[k*H + j] -> g_Wpack[(g*H+j)*HX + k]
// ---------------------------------------------------------------------------
__global__ void pack_weights(const float* __restrict__ Wf, const float* __restrict__ Wi,
                             const float* __restrict__ Wc, const float* __restrict__ Wo) {
    __shared__ float tile[32][33];
    const int g  = blockIdx.z;
    const float* W = (g == 0) ? Wf : (g == 1) ? Wi : (g == 2) ? Wc : Wo;
    const int j0 = blockIdx.x * 32;
    const int k0 = blockIdx.y * 32;
    const int tx = threadIdx.x, ty0 = threadIdx.y;
    #pragma unroll
    for (int ty = ty0; ty < 32; ty += 8)
        tile[ty][tx] = W[(size_t)(k0 + ty) * HH + (j0 + tx)];
    __syncthreads();
    #pragma unroll
    for (int ty = ty0; ty < 32; ty += 8)
        g_Wpack[(size_t)(g * HH + j0 + ty) * HXX + (k0 + tx)] = tile[tx][ty];
}

// ---------------------------------------------------------------------------
// Chunk staging. k0 < 512 -> h (from out[t-1], zeros at t=0); else x[t].
// 2048 float4 per chunk, 512 threads -> 4 each. h reads via __ldcv (L2 path:
// lines are cold anyway; avoids any L1 staleness under the custom barrier).
// ---------------------------------------------------------------------------
__device__ __forceinline__ void ld_chunk(float4 p[4], const float* __restrict__ x,
                                         const float* out, int t, int k0, int tid) {
    if (k0 < 512) {
        if (t == 0) {
            #pragma unroll
            for (int j = 0; j < 4; j++) p[j] = make_float4(0.f, 0.f, 0.f, 0.f);
        } else {
            const float* src = out + (size_t)(t - 1) * (BB * HH) + k0;
            #pragma unroll
            for (int j = 0; j < 4; j++) {
                const int idx = tid + j * NTHR, b = idx >> 4, q = idx & 15;
                p[j] = __ldcv((const float4*)(src + (size_t)b * HH + q * 4));
            }
        }
    } else {
        const float* src = x + (size_t)t * (BB * II) + (k0 - 512);
        #pragma unroll
        for (int j = 0; j < 4; j++) {
            const int idx = tid + j * NTHR, b = idx >> 4, q = idx & 15;
            p[j] = __ldg((const float4*)(src + (size_t)b * II + q * 4));
        }
    }
}

__device__ __forceinline__ void st_chunk(float* vh, const float4 p[4], int tid) {
    #pragma unroll
    for (int j = 0; j < 4; j++) {
        const int idx = tid + j * NTHR, b = idx >> 4, q = idx & 15;
        *(float4*)(vh + b * VROW + q * 4) = p[j];
    }
}

// ---------------------------------------------------------------------------
// Persistent kernel: weights stay in SMEM; per-step grid barrier via L2 atomic.
// Thread map: kg = tid>>8 (k-half), tx = tid&7 (2 gate-cols), ty = (tid&255)>>3
// (owns b = ty + 32*bi).
// ---------------------------------------------------------------------------
__global__ void __launch_bounds__(NTHR, 1)
lstm_persist(const float* __restrict__ x,
             const float* __restrict__ bf, const float* __restrict__ bi_,
             const float* __restrict__ bc, const float* __restrict__ bo,
             float* out)
{
    extern __shared__ float sm[];
    float* Ws  = sm;                 // [GCN][WROW]
    float* vsm = sm + WS_ELEMS;      // 4 x [BB][VROW]  (buf x kg)

    const int tid = threadIdx.x;
    const int cid = blockIdx.x;
    const int j0  = cid * JPC;
    const int kg  = tid >> 8;
    const int r   = tid & 255;
    const int tx  = r & 7;
    const int ty  = r >> 3;

    // Stage this CTA's 16 weight columns once (49KB), coalesced from packed layout.
    {
        const float4* wp = (const float4*)g_Wpack;
        #pragma unroll
        for (int it = 0; it < (GCN * (HXX / 4)) / NTHR; ++it) {   // 6 iters
            const int idx = tid + it * NTHR;
            const int gc  = idx / (HXX / 4);
            const int k4  = idx % (HXX / 4);
            const int g = gc >> 2, jj = gc & 3;
            *(float4*)(Ws + gc * WROW + k4 * 4) =
                wp[(size_t)(g * HH + j0 + jj) * (HXX / 4) + k4];
        }
    }

    // Bias for this thread's two gate-cols (added once, in kg==0's accumulators).
    unsigned long long ub[2];
    #pragma unroll
    for (int gci = 0; gci < 2; gci++) {
        const int gc = 2 * tx + gci;
        const int g = gc >> 2, jj = gc & 3;
        const float* bp = (g == 0) ? bf : (g == 1) ? bi_ : (g == 2) ? bc : bo;
        ub[gci] = (kg == 0)
                ? (unsigned long long)__float_as_uint(bp[j0 + jj]) : 0ull;
    }
    __syncthreads();

    for (int t = 0; t < TT; ++t) {
        unsigned long long acc[2][4];
        #pragma unroll
        for (int gci = 0; gci < 2; gci++)
            #pragma unroll
            for (int bi = 0; bi < 4; bi++) acc[gci][bi] = ub[gci];

        float4 pA[4], pB[4];
        ld_chunk(pA, x, out, t, 0, tid);
        ld_chunk(pB, x, out, t, 384, tid);
        st_chunk(vsm + 0 * VS_HALF, pA, tid);
        st_chunk(vsm + 1 * VS_HALF, pB, tid);
        __syncthreads();

        for (int i = 0; i < 6; ++i) {
            const int buf = i & 1;
            if (i < 5) {
                ld_chunk(pA, x, out, t, (i + 1) * KC, tid);
                ld_chunk(pB, x, out, t, 384 + (i + 1) * KC, tid);
            }
            const float* wr0 = Ws + (2 * tx) * WROW + kg * 384 + i * KC;
            const float* wr1 = wr0 + WROW;
            const float* vb  = vsm + (buf * 2 + kg) * VS_HALF + ty * VROW;

            #pragma unroll
            for (int kk = 0; kk < KC; kk += 4) {
                const ulonglong2 w0 = *(const ulonglong2*)(wr0 + kk);
                const ulonglong2 w1 = *(const ulonglong2*)(wr1 + kk);
                #pragma unroll
                for (int bi = 0; bi < 4; bi++) {
                    const ulonglong2 v = *(const ulonglong2*)(vb + bi * (32 * VROW) + kk);
                    FMA2(acc[0][bi], w0.x, v.x);
                    FMA2(acc[0][bi], w0.y, v.y);
                    FMA2(acc[1][bi], w1.x, v.x);
                    FMA2(acc[1][bi], w1.y, v.y);
                }
            }
            if (i < 5) {
                st_chunk(vsm + ((buf ^ 1) * 2 + 0) * VS_HALF, pA, tid);
                st_chunk(vsm + ((buf ^ 1) * 2 + 1) * VS_HALF, pB, tid);
                __syncthreads();
            }
        }

        // Partial-sum exchange: gsm[kg][gc][b] in low smem region (unused by i=5).
        float* gsm = vsm;   // 2*16*128 floats = 16KB
        #pragma unroll
        for (int gci = 0; gci < 2; gci++)
            #pragma unroll
            for (int bi = 0; bi < 4; bi++) {
                const unsigned long long a = acc[gci][bi];
                const float lo = __uint_as_float((unsigned)(a & 0xffffffffu));
                const float hi = __uint_as_float((unsigned)(a >> 32));
                gsm[(kg * GCN + 2 * tx + gci) * BB + (ty + 32 * bi)] = lo + hi;
            }
        __syncthreads();

        // Elementwise LSTM update: 512 cells/CTA, 1 per thread.
        {
            const int jj = tid >> 7, b = tid & 127;
            const float fg = gsm[(0 * 4 + jj) * BB + b] + gsm[(GCN + 0 * 4 + jj) * BB + b];
            const float ig = gsm[(1 * 4 + jj) * BB + b] + gsm[(GCN + 1 * 4 + jj) * BB + b];
            const float cg = gsm[(2 * 4 + jj) * BB + b] + gsm[(GCN + 2 * 4 + jj) * BB + b];
            const float og = gsm[(3 * 4 + jj) * BB + b] + gsm[(GCN + 3 * 4 + jj) * BB + b];
            const float fs = 1.0f / (1.0f + expf(-fg));
            const float is = 1.0f / (1.0f + expf(-ig));
            const float os = 1.0f / (1.0f + expf(-og));
            const float Cold = (t == 0) ? 0.0f : g_C[b * HH + j0 + jj];
            const float Cnew = fs * Cold + is * tanhf(cg);
            g_C[b * HH + j0 + jj] = Cnew;
            out[(size_t)t * (BB * HH) + (size_t)b * HH + j0 + jj] = os * tanhf(Cnew);
        }

        // Grid-wide barrier (release arrive / acquire poll). All 128 CTAs resident.
        if (t < TT - 1) {
            __threadfence();
            __syncthreads();
            if (tid == 0) {
                asm volatile("red.release.gpu.global.add.u32 [%0], %1;"
                             :: "l"(&g_bar), "r"(1u) : "memory");
                const unsigned target = (unsigned)NCTA * (unsigned)(t + 1);
                unsigned v;
                do {
                    asm volatile("ld.acquire.gpu.global.u32 %0, [%1];"
                                 : "=r"(v) : "l"(&g_bar) : "memory");
                } while (v < target);
            }
            __syncthreads();
        }
    }
}

// ---------------------------------------------------------------------------
extern "C" void kernel_launch(void* const* d_in, const int* in_sizes, int n_in,
                              void* d_out, int out_size) {
    (void)in_sizes; (void)n_in; (void)out_size;
    const float* x  = (const float*)d_in[0];
    const float* Wf = (const float*)d_in[1];
    const float* bf = (const float*)d_in[2];
    const float* Wi = (const float*)d_in[3];
    const float* bi = (const float*)d_in[4];
    const float* Wc = (const float*)d_in[5];
    const float* bc = (const float*)d_in[6];
    const float* Wo = (const float*)d_in[7];
    const float* bo = (const float*)d_in[8];
    float* out = (float*)d_out;

    cudaFuncSetAttribute(lstm_persist, cudaFuncAttributeMaxDynamicSharedMemorySize, SMEM_BYTES);

    reset_bar<<<1, 1>>>();
    pack_weights<<<dim3(HH / 32, HXX / 32, 4), dim3(32, 8)>>>(Wf, Wi, Wc, Wo);
    lstm_persist<<<NCTA, NTHR, SMEM_BYTES>>>(x, bf, bi, bc, bo, out);
}

// round 9
// speedup vs baseline: 2.0262x; 1.4507x over previous
#include <cuda_runtime.h>
#include <cstdint>

#define TT   512
#define BB   128
#define II   256
#define HH   512
#define HXX  768
#define NCTA 128      // one CTA per 4 H-columns; all co-resident (<=148 SMs)
#define JPC  4
#define GCN  16       // gate-cols per CTA (4 gates * 4 cols)
#define NTHR 512      // 4 k-groups x 128 threads
#define KG   4
#define KPG  192      // k per group
#define KC   32       // k window per iteration (6 iterations)
#define WROW 772      // padded weight row (768+4): 772*4 B % 128 = 16 -> conflict-free
#define VROW 36       // padded v row (32+4):       36*4 B % 128 = 16 -> conflict-free
#define VS_ELEMS (KG * BB * VROW)       // 18432 floats per buffer
#define WS_ELEMS (GCN * WROW)           // 12352 floats
#define SMEM_FLOATS (WS_ELEMS + 2 * VS_ELEMS)
#define SMEM_BYTES  (SMEM_FLOATS * 4)   // 196864 B (< 227KB cap)

// Device scratch (no allocations allowed anywhere).
__device__ float    g_C[BB * HH];
__device__ float    g_Wpack[4 * HH * HXX];   // [g][j][k], k contiguous
__device__ unsigned g_bar;

// f32x2 packed FMA (FFMA2): 2 MACs/instr.
#define FMA2(acc, a, b) \
    asm("fma.rn.f32x2 %0, %1, %2, %0;" : "+l"(acc) : "l"(a), "l"(b))

// Fast, NaN-safe activations (accuracy budget: need <1e-3, these give ~1e-6).
__device__ __forceinline__ float fsigm(float x) {
    float e; asm("ex2.approx.f32 %0, %1;" : "=f"(e) : "f"(-1.4426950408889634f * x));
    float r; asm("rcp.approx.f32 %0, %1;" : "=f"(r) : "f"(1.0f + e));
    return r;   // x<<0: e->inf, r->0 OK; x>>0: e->0, r->1 OK
}
__device__ __forceinline__ float ftanh(float x) {
    float ax = fabsf(x);
    float e; asm("ex2.approx.f32 %0, %1;" : "=f"(e) : "f"(-2.885390081777927f * ax));
    float r; asm("rcp.approx.f32 %0, %1;" : "=f"(r) : "f"(1.0f + e));
    return copysignf((1.0f - e) * r, x);   // e in (0,1]: no inf/NaN
}

// ---------------------------------------------------------------------------
// One-time weight transpose: Wg[k*H + j] -> g_Wpack[(g*H+j)*HX + k].
// Also resets the grid barrier (block (0,0,0), thread 0).
// ---------------------------------------------------------------------------
__global__ void pack_weights(const float* __restrict__ Wf, const float* __restrict__ Wi,
                             const float* __restrict__ Wc, const float* __restrict__ Wo) {
    if (blockIdx.x == 0 && blockIdx.y == 0 && blockIdx.z == 0 &&
        threadIdx.x == 0 && threadIdx.y == 0) g_bar = 0u;
    __shared__ float tile[32][33];
    const int g  = blockIdx.z;
    const float* W = (g == 0) ? Wf : (g == 1) ? Wi : (g == 2) ? Wc : Wo;
    const int j0 = blockIdx.x * 32;
    const int k0 = blockIdx.y * 32;
    const int tx = threadIdx.x, ty0 = threadIdx.y;
    #pragma unroll
    for (int ty = ty0; ty < 32; ty += 8)
        tile[ty][tx] = W[(size_t)(k0 + ty) * HH + (j0 + tx)];
    __syncthreads();
    #pragma unroll
    for (int ty = ty0; ty < 32; ty += 8)
        g_Wpack[(size_t)(g * HH + j0 + ty) * HXX + (k0 + tx)] = tile[tx][ty];
}

// ---------------------------------------------------------------------------
// Stage iteration i: for each kg, the 32-k window at k0 = kg*192 + i*32.
// Windows never straddle the h/x boundary (512 = 384 + 4*32).
// 4096 float4 total, 512 threads -> 8 each.
// ---------------------------------------------------------------------------
__device__ __forceinline__ void ld_stage(float4 p[8], const float* __restrict__ x,
                                         const float* out, int t, int i, int tid) {
    #pragma unroll
    for (int j = 0; j < 8; j++) {
        const int idx = tid + j * NTHR;
        const int kgw = idx >> 10;
        const int rem = idx & 1023;
        const int b   = rem >> 3;
        const int q   = rem & 7;
        const int k0  = kgw * KPG + i * KC;
        if (k0 < 512) {   // h source (zeros at t=0)
            if (t == 0) p[j] = make_float4(0.f, 0.f, 0.f, 0.f);
            else p[j] = __ldcv((const float4*)(out + (size_t)(t - 1) * (BB * HH)
                                               + (size_t)b * HH + k0 + q * 4));
        } else {          // x source
            p[j] = __ldg((const float4*)(x + (size_t)t * (BB * II)
                                         + (size_t)b * II + (k0 - 512) + q * 4));
        }
    }
}

__device__ __forceinline__ void st_stage(float* vbuf, const float4 p[8], int tid) {
    #pragma unroll
    for (int j = 0; j < 8; j++) {
        const int idx = tid + j * NTHR;
        const int kgw = idx >> 10;
        const int rem = idx & 1023;
        const int b   = rem >> 3;
        const int q   = rem & 7;
        *(float4*)(vbuf + (kgw * BB + b) * VROW + q * 4) = p[j];
    }
}

// ---------------------------------------------------------------------------
// Persistent kernel. Thread map: kg = tid>>7; r = tid&127; tx = r&3 (covers
// gc = tx + 4*gi, i.e. H-col j0+tx across all 4 gates); ty = r>>2 (b = ty+32*bi).
// ---------------------------------------------------------------------------
__global__ void __launch_bounds__(NTHR, 1)
lstm_persist(const float* __restrict__ x,
             const float* __restrict__ bf, const float* __restrict__ bi_,
             const float* __restrict__ bc, const float* __restrict__ bo,
             float* out)
{
    extern __shared__ float sm[];
    float* Ws  = sm;                 // [GCN][WROW]
    float* vsm = sm + WS_ELEMS;      // 2 x [KG][BB][VROW]

    const int tid = threadIdx.x;
    const int cid = blockIdx.x;
    const int j0  = cid * JPC;
    const int kg  = tid >> 7;
    const int r   = tid & 127;
    const int tx  = r & 3;
    const int ty  = r >> 2;

    // Stage this CTA's 16 weight columns once (49KB), coalesced.
    {
        const float4* wp = (const float4*)g_Wpack;
        #pragma unroll
        for (int it = 0; it < (GCN * (HXX / 4)) / NTHR; ++it) {   // 6 iters
            const int idx = tid + it * NTHR;
            const int gc  = idx / (HXX / 4);
            const int k4  = idx % (HXX / 4);
            const int g = gc >> 2, jj = gc & 3;
            *(float4*)(Ws + gc * WROW + k4 * 4) =
                wp[(size_t)(g * HH + j0 + jj) * (HXX / 4) + k4];
        }
    }

    // Bias per gate (thread covers col j0+tx of all 4 gates); added in kg==0 only.
    unsigned long long ub[4];
    #pragma unroll
    for (int gi = 0; gi < 4; gi++) {
        const float* bp = (gi == 0) ? bf : (gi == 1) ? bi_ : (gi == 2) ? bc : bo;
        ub[gi] = (kg == 0) ? (unsigned long long)__float_as_uint(bp[j0 + tx]) : 0ull;
    }
    __syncthreads();

    const float* wthr = Ws + tx * WROW + kg * KPG;   // +gi*4*WROW per gate

    for (int t = 0; t < TT; ++t) {
        unsigned long long acc[4][4];
        #pragma unroll
        for (int gi = 0; gi < 4; gi++)
            #pragma unroll
            for (int bi = 0; bi < 4; bi++) acc[gi][bi] = ub[gi];

        float4 p[8];
        ld_stage(p, x, out, t, 0, tid);
        st_stage(vsm, p, tid);
        __syncthreads();

        #pragma unroll 1
        for (int i = 0; i < 6; ++i) {
            const int buf = i & 1;
            if (i < 5) ld_stage(p, x, out, t, i + 1, tid);

            const float* wr = wthr + i * KC;
            const float* vb = vsm + buf * VS_ELEMS + (kg * BB + ty) * VROW;

            #pragma unroll
            for (int kk = 0; kk < KC; kk += 4) {
                ulonglong2 w[4], v[4];
                #pragma unroll
                for (int gi = 0; gi < 4; gi++)
                    w[gi] = *(const ulonglong2*)(wr + gi * (4 * WROW) + kk);
                #pragma unroll
                for (int bi = 0; bi < 4; bi++)
                    v[bi] = *(const ulonglong2*)(vb + bi * (32 * VROW) + kk);
                #pragma unroll
                for (int gi = 0; gi < 4; gi++)
                    #pragma unroll
                    for (int bi = 0; bi < 4; bi++) {
                        FMA2(acc[gi][bi], w[gi].x, v[bi].x);
                        FMA2(acc[gi][bi], w[gi].y, v[bi].y);
                    }
            }
            if (i < 5) {
                st_stage(vsm + (buf ^ 1) * VS_ELEMS, p, tid);
                __syncthreads();
            }
        }

        // kg-partial exchange: gsm[kg][gc][b] (32KB) in buffer-0 region
        // (last compute read buffer 1 — disjoint).
        float* gsm = vsm;
        #pragma unroll
        for (int gi = 0; gi < 4; gi++)
            #pragma unroll
            for (int bi = 0; bi < 4; bi++) {
                const unsigned long long a = acc[gi][bi];
                const float lo = __uint_as_float((unsigned)(a & 0xffffffffu));
                const float hi = __uint_as_float((unsigned)(a >> 32));
                gsm[((kg * GCN) + (gi * 4 + tx)) * BB + (ty + 32 * bi)] = lo + hi;
            }
        __syncthreads();

        // Elementwise update: 512 cells/CTA, 1 per thread; reduce 4 kg partials.
        {
            const int b = tid & 127, jj = tid >> 7;
            float gate[4];
            #pragma unroll
            for (int gi = 0; gi < 4; gi++) {
                float s = 0.f;
                #pragma unroll
                for (int k = 0; k < KG; k++)
                    s += gsm[(k * GCN + gi * 4 + jj) * BB + b];
                gate[gi] = s;
            }
            const float fs = fsigm(gate[0]);
            const float is = fsigm(gate[1]);
            const float os = fsigm(gate[3]);
            const float Cold = (t == 0) ? 0.0f : g_C[b * HH + j0 + jj];
            const float Cnew = fs * Cold + is * ftanh(gate[2]);
            g_C[b * HH + j0 + jj] = Cnew;
            out[(size_t)t * (BB * HH) + (size_t)b * HH + j0 + jj] = os * ftanh(Cnew);
        }

        // Grid barrier. bar.sync + red.release gives transitive release of all
        // threads' prior stores; consumer side: acquire + bar.sync.
        if (t < TT - 1) {
            __syncthreads();
            if (tid == 0) {
                asm volatile("red.release.gpu.global.add.u32 [%0], %1;"
                             :: "l"(&g_bar), "r"(1u) : "memory");
                const unsigned target = (unsigned)NCTA * (unsigned)(t + 1);
                unsigned v;
                do {
                    asm volatile("ld.acquire.gpu.global.u32 %0, [%1];"
                                 : "=r"(v) : "l"(&g_bar) : "memory");
                } while (v < target);
            }
            __syncthreads();
        }
    }
}

// ---------------------------------------------------------------------------
extern "C" void kernel_launch(void* const* d_in, const int* in_sizes, int n_in,
                              void* d_out, int out_size) {
    (void)in_sizes; (void)n_in; (void)out_size;
    const float* x  = (const float*)d_in[0];
    const float* Wf = (const float*)d_in[1];
    const float* bf = (const float*)d_in[2];
    const float* Wi = (const float*)d_in[3];
    const float* bi = (const float*)d_in[4];
    const float* Wc = (const float*)d_in[5];
    const float* bc = (const float*)d_in[6];
    const float* Wo = (const float*)d_in[7];
    const float* bo = (const float*)d_in[8];
    float* out = (float*)d_out;

    cudaFuncSetAttribute(lstm_persist, cudaFuncAttributeMaxDynamicSharedMemorySize, SMEM_BYTES);

    // Exactly 2 launches per call: pack_weights (also resets barrier), persist.
    pack_weights<<<dim3(HH / 32, HXX / 32, 4), dim3(32, 8)>>>(Wf, Wi, Wc, Wo);
    lstm_persist<<<NCTA, NTHR, SMEM_BYTES>>>(x, bf, bi, bc, bo, out);
}